// round 17
// baseline (speedup 1.0000x reference)
#include <cuda_runtime.h>
#include <cuda_bf16.h>
#include <cstdint>

#define BATCH 8
#define MDIM  2048
#define NDIM  2048
#define DDIM  1024

// ---------------- device scratch ----------------
__device__ float         g_St  [(size_t)BATCH * NDIM * MDIM];   // St[b][n][m] fp32
__device__ __nv_bfloat16 g_xh  [(size_t)BATCH * MDIM * DDIM];
__device__ __nv_bfloat16 g_xl  [(size_t)BATCH * MDIM * DDIM];
__device__ __nv_bfloat16 g_yh  [(size_t)BATCH * NDIM * DDIM];
__device__ __nv_bfloat16 g_yl  [(size_t)BATCH * NDIM * DDIM];
__device__ __nv_bfloat16 g_Eth [(size_t)BATCH * NDIM * MDIM];
__device__ __nv_bfloat16 g_Etl [(size_t)BATCH * NDIM * MDIM];
__device__ __nv_bfloat16 g_xsth[(size_t)BATCH * DDIM * MDIM];   // (x/s)^T [b][d][m]
__device__ __nv_bfloat16 g_xstl[(size_t)BATCH * DDIM * MDIM];
__device__ unsigned      g_cmax[BATCH * MDIM];
__device__ float         g_sum [BATCH * MDIM];

// ---------------- helpers ----------------
__device__ __forceinline__ uint32_t smem_u32(const void* p) {
    return (uint32_t)__cvta_generic_to_shared(p);
}
__device__ __forceinline__ void cp16(uint32_t s, const void* g) {
    asm volatile("cp.async.cg.shared.global [%0], [%1], 16;" :: "r"(s), "l"(g));
}
__device__ __forceinline__ void mma16816(float* c, const uint32_t* a, const uint32_t* b) {
    asm volatile(
        "mma.sync.aligned.m16n8k16.row.col.f32.bf16.bf16.f32 "
        "{%0,%1,%2,%3}, {%4,%5,%6,%7}, {%8,%9}, {%0,%1,%2,%3};"
        : "+f"(c[0]), "+f"(c[1]), "+f"(c[2]), "+f"(c[3])
        : "r"(a[0]), "r"(a[1]), "r"(a[2]), "r"(a[3]), "r"(b[0]), "r"(b[1]));
}
#define LDM4(r0, r1, r2, r3, addr) \
    asm volatile("ldmatrix.sync.aligned.m8n8.x4.shared.b16 {%0,%1,%2,%3}, [%4];" \
                 : "=r"(r0), "=r"(r1), "=r"(r2), "=r"(r3) : "r"(addr))

// monotone float<->uint encoding for atomicMax
__device__ __forceinline__ unsigned fenc(float f) {
    unsigned u = __float_as_uint(f);
    return (u & 0x80000000u) ? ~u : (u | 0x80000000u);
}
__device__ __forceinline__ float fdec(unsigned u) {
    return __uint_as_float((u & 0x80000000u) ? (u ^ 0x80000000u) : ~u);
}

// ---------------- GEMM (mma.sync bf16 x3 split, 4-stage pipeline) ----------------
// C[i][j] = sum_k A[i][k]*B[j][k]; A tile 128 rows (blockIdx.y), B tile 128 rows
// (blockIdx.x). BK=16, smem rows padded to 24 halves (48B):
//  - ldmatrix phases: 16B slot index 3r+c mod 8 distinct over 8 rows -> conflict-free
//  - global loads: EXACTLY 2 x 16B per row (the valid 32B k-slice); smem bytes
//    32..47 of each row are padding, never read (ldmatrix cols are 0/8 halves).
#define BK     16
#define LDA    24                          // halves per smem row (48B)
#define TILE_B (128 * 48)                  // bytes per tile (6144)
#define STG_B  (4 * TILE_B)                // bytes per stage (Ah,Al,Bh,Bl) = 24576
#define NSTG   4
#define GEMM_SMEM (NSTG * STG_B)           // 98304 bytes

// load one full stage (4 tiles) for k-slice k0; 4 cp16 per thread
__device__ __forceinline__ void ldstage(
    const __nv_bfloat16* ah, const __nv_bfloat16* al,
    const __nv_bfloat16* bh, const __nv_bfloat16* bl,
    int K, int k0, uint32_t sb, int tid)
{
    #pragma unroll
    for (int i = 0; i < 4; i++) {
        int s = i * 256 + tid;                 // 0..1023
        int row = s >> 1, c = s & 1;           // row 0..511, chunk 0..1 (16B each)
        int t = row >> 7, r = row & 127;
        const __nv_bfloat16* base = (t == 0) ? ah : (t == 1) ? al : (t == 2) ? bh : bl;
        cp16(sb + (uint32_t)(row * 48 + c * 16),
             (const char*)(base + (size_t)r * K + k0) + c * 16);
    }
}

template<bool CMAX>
__global__ void __launch_bounds__(256, 2)
gemm_bf16x3(const __nv_bfloat16* __restrict__ Ah, const __nv_bfloat16* __restrict__ Al,
            const __nv_bfloat16* __restrict__ Bh, const __nv_bfloat16* __restrict__ Bl,
            float* __restrict__ C, unsigned* __restrict__ cmax,
            int K, size_t sAb, size_t sBb, size_t sCb, int ldC)
{
    extern __shared__ __nv_bfloat16 sm[];
    const int tid  = threadIdx.x;
    const int warp = tid >> 5, lane = tid & 31;
    const int g = lane >> 2, tg = lane & 3;
    const int m_w = (warp >> 2) * 64;    // 0/64  (C row offset)
    const int n_w = (warp & 3) * 32;     // 0/32/64/96 (C col offset)

    const int b  = blockIdx.z;
    const int i0 = blockIdx.y * 128;
    const int j0 = blockIdx.x * 128;

    const __nv_bfloat16* ah = Ah + (size_t)b * sAb + (size_t)i0 * K;
    const __nv_bfloat16* al = Al + (size_t)b * sAb + (size_t)i0 * K;
    const __nv_bfloat16* bh = Bh + (size_t)b * sBb + (size_t)j0 * K;
    const __nv_bfloat16* bl = Bl + (size_t)b * sBb + (size_t)j0 * K;

    const uint32_t sb0 = smem_u32(sm);

    // ldmatrix per-lane offsets (bytes within a tile)
    const int p  = lane >> 3;            // piece 0..3
    const int rr = lane & 7;
    // A x4: pieces {(m,k0),(m+8,k0),(m,k8),(m+8,k8)}
    const uint32_t aoff = (uint32_t)(((m_w + (p & 1) * 8 + rr) * LDA + (p >> 1) * 8) * 2);
    // B x4: pieces {(j,k0),(j,k8),(j+1,k0),(j+1,k8)}
    const uint32_t boff = (uint32_t)(((n_w + ((lane >> 4) & 1) * 8 + rr) * LDA
                                      + ((lane >> 3) & 1) * 8) * 2);

    float acc[4][4][4];
    #pragma unroll
    for (int i = 0; i < 4; i++)
        #pragma unroll
        for (int j = 0; j < 4; j++)
            #pragma unroll
            for (int q = 0; q < 4; q++) acc[i][j][q] = 0.f;

    const int NT = K / BK;

    // prologue: stages 0..2
    #pragma unroll
    for (int pl = 0; pl < 3; pl++) {
        ldstage(ah, al, bh, bl, K, pl * BK, sb0 + (uint32_t)(pl * STG_B), tid);
        asm volatile("cp.async.commit_group;" ::: "memory");
    }

    for (int kt = 0; kt < NT; kt++) {
        asm volatile("cp.async.wait_group 2;" ::: "memory");   // stage kt complete
        __syncthreads();                                       // prev compute done everywhere

        int kp = kt + 3;
        if (kp < NT)
            ldstage(ah, al, bh, bl, K, kp * BK,
                    sb0 + (uint32_t)((kp & 3) * STG_B), tid);
        asm volatile("cp.async.commit_group;" ::: "memory");   // unconditional (empty ok)

        const uint32_t st  = sb0 + (uint32_t)((kt & 3) * STG_B);
        const uint32_t aHb = st;
        const uint32_t aLb = st + TILE_B;
        const uint32_t bHb = st + 2 * TILE_B;
        const uint32_t bLb = st + 3 * TILE_B;

        uint32_t fbh[4][2], fbl[4][2];
        LDM4(fbh[0][0], fbh[0][1], fbh[1][0], fbh[1][1], bHb + boff);
        LDM4(fbh[2][0], fbh[2][1], fbh[3][0], fbh[3][1], bHb + boff + 16 * LDA * 2);
        LDM4(fbl[0][0], fbl[0][1], fbl[1][0], fbl[1][1], bLb + boff);
        LDM4(fbl[2][0], fbl[2][1], fbl[3][0], fbl[3][1], bLb + boff + 16 * LDA * 2);

        #pragma unroll
        for (int i = 0; i < 4; i++) {
            const uint32_t iadd = (uint32_t)(i * 16 * LDA * 2);
            uint32_t fa[4], fl[4];
            LDM4(fa[0], fa[1], fa[2], fa[3], aHb + aoff + iadd);
            LDM4(fl[0], fl[1], fl[2], fl[3], aLb + aoff + iadd);
            #pragma unroll
            for (int j = 0; j < 4; j++) {
                mma16816(acc[i][j], fa, fbh[j]);
                mma16816(acc[i][j], fa, fbl[j]);
                mma16816(acc[i][j], fl, fbh[j]);
            }
        }
    }
    asm volatile("cp.async.wait_group 0;" ::: "memory");

    // optional fused column-max (over C rows = n) per column (= m), for softmax
    if (CMAX) {
        #pragma unroll
        for (int j = 0; j < 4; j++) {
            float cm0 = -3.4e38f, cm1 = -3.4e38f;
            #pragma unroll
            for (int i = 0; i < 4; i++) {
                cm0 = fmaxf(cm0, fmaxf(acc[i][j][0], acc[i][j][2]));
                cm1 = fmaxf(cm1, fmaxf(acc[i][j][1], acc[i][j][3]));
            }
            #pragma unroll
            for (int off = 4; off <= 16; off <<= 1) {
                cm0 = fmaxf(cm0, __shfl_xor_sync(0xffffffffu, cm0, off));
                cm1 = fmaxf(cm1, __shfl_xor_sync(0xffffffffu, cm1, off));
            }
            if (g == 0) {
                int c0 = j0 + n_w + j * 8 + tg * 2;
                atomicMax(&cmax[b * ldC + c0],     fenc(cm0));
                atomicMax(&cmax[b * ldC + c0 + 1], fenc(cm1));
            }
        }
    }

    // epilogue
    float* Cb = C + (size_t)b * sCb;
    #pragma unroll
    for (int i = 0; i < 4; i++) {
        int r0 = i0 + m_w + i * 16 + g;
        #pragma unroll
        for (int j = 0; j < 4; j++) {
            int c0 = j0 + n_w + j * 8 + tg * 2;
            float2 v0 = {acc[i][j][0], acc[i][j][1]};
            float2 v1 = {acc[i][j][2], acc[i][j][3]};
            *(float2*)(Cb + (size_t)r0 * ldC + c0)       = v0;
            *(float2*)(Cb + (size_t)(r0 + 8) * ldC + c0) = v1;
        }
    }
}

// ---------------- aux kernels ----------------
__global__ void __launch_bounds__(256)
init_stats_kernel()
{
    int i = blockIdx.x * 256 + threadIdx.x;
    if (i < BATCH * MDIM) { g_cmax[i] = 0u; g_sum[i] = 0.f; }
}

__global__ void __launch_bounds__(256)
split_kernel(const float* __restrict__ in, __nv_bfloat16* __restrict__ h,
             __nv_bfloat16* __restrict__ l)
{
    size_t i = ((size_t)blockIdx.x * 256 + threadIdx.x) * 4;
    float4 v = *(const float4*)(in + i);
    __nv_bfloat16 h0 = __float2bfloat16(v.x), h1 = __float2bfloat16(v.y);
    __nv_bfloat16 h2 = __float2bfloat16(v.z), h3 = __float2bfloat16(v.w);
    __nv_bfloat16 l0 = __float2bfloat16(v.x - __bfloat162float(h0));
    __nv_bfloat16 l1 = __float2bfloat16(v.y - __bfloat162float(h1));
    __nv_bfloat16 l2 = __float2bfloat16(v.z - __bfloat162float(h2));
    __nv_bfloat16 l3 = __float2bfloat16(v.w - __bfloat162float(h3));
    __nv_bfloat162* hp = (__nv_bfloat162*)(h + i);
    __nv_bfloat162* lp = (__nv_bfloat162*)(l + i);
    hp[0] = __nv_bfloat162(h0, h1); hp[1] = __nv_bfloat162(h2, h3);
    lp[0] = __nv_bfloat162(l0, l1); lp[1] = __nv_bfloat162(l2, l3);
}

// Et = exp(St - colmax) split to bf16 hi/lo; partial column sums
__global__ void __launch_bounds__(256)
exp_kernel()
{
    const int b  = blockIdx.z;
    const int m  = blockIdx.x * 256 + threadIdx.x;
    const int n0 = blockIdx.y * 128;
    const float mx = fdec(g_cmax[b * MDIM + m]);
    const size_t base = ((size_t)b * NDIM + n0) * MDIM + m;
    float s = 0.f;
    #pragma unroll 4
    for (int i = 0; i < 128; i++) {
        size_t idx = base + (size_t)i * MDIM;
        float e = __expf(g_St[idx] - mx);
        s += e;
        __nv_bfloat16 h = __float2bfloat16(e);
        __nv_bfloat16 l = __float2bfloat16(e - __bfloat162float(h));
        g_Eth[idx] = h;
        g_Etl[idx] = l;
    }
    atomicAdd(&g_sum[b * MDIM + m], s);
}

// xst[b][d][m] = x[b][m][d] / sum[b][m], split to bf16 hi/lo (32x32 transpose)
__global__ void __launch_bounds__(256)
xst_kernel(const float* __restrict__ x)
{
    __shared__ float t[32][33];
    __shared__ float sinv[32];
    const int b  = blockIdx.z;
    const int d0 = blockIdx.x * 32;
    const int m0 = blockIdx.y * 32;
    const int tx = threadIdx.x & 31, ty = threadIdx.x >> 5;

    #pragma unroll
    for (int r = ty; r < 32; r += 8)
        t[r][tx] = x[((size_t)b * MDIM + (m0 + r)) * DDIM + d0 + tx];
    if (ty == 0) sinv[tx] = 1.0f / g_sum[b * MDIM + m0 + tx];
    __syncthreads();

    #pragma unroll
    for (int r = ty; r < 32; r += 8) {
        float v = t[tx][r] * sinv[tx];
        __nv_bfloat16 h = __float2bfloat16(v);
        __nv_bfloat16 l = __float2bfloat16(v - __bfloat162float(h));
        size_t o = ((size_t)b * DDIM + (d0 + r)) * MDIM + m0 + tx;
        g_xsth[o] = h;
        g_xstl[o] = l;
    }
}

// ---------------- host ----------------
extern "C" void kernel_launch(void* const* d_in, const int* in_sizes, int n_in,
                              void* d_out, int out_size)
{
    const float* x = (const float*)d_in[0];   // [B,M,D]
    const float* y = (const float*)d_in[1];   // [B,N,D]
    float* out = (float*)d_out;               // [B,N,D]

    cudaFuncSetAttribute(gemm_bf16x3<true>,
                         cudaFuncAttributeMaxDynamicSharedMemorySize, GEMM_SMEM);
    cudaFuncSetAttribute(gemm_bf16x3<false>,
                         cudaFuncAttributeMaxDynamicSharedMemorySize, GEMM_SMEM);

    float* St;
    unsigned* cmax;
    __nv_bfloat16 *xh, *xl, *yh, *yl, *Eth, *Etl, *xsth, *xstl;
    cudaGetSymbolAddress((void**)&St,   g_St);
    cudaGetSymbolAddress((void**)&cmax, g_cmax);
    cudaGetSymbolAddress((void**)&xh,   g_xh);
    cudaGetSymbolAddress((void**)&xl,   g_xl);
    cudaGetSymbolAddress((void**)&yh,   g_yh);
    cudaGetSymbolAddress((void**)&yl,   g_yl);
    cudaGetSymbolAddress((void**)&Eth,  g_Eth);
    cudaGetSymbolAddress((void**)&Etl,  g_Etl);
    cudaGetSymbolAddress((void**)&xsth, g_xsth);
    cudaGetSymbolAddress((void**)&xstl, g_xstl);

    init_stats_kernel<<<(BATCH * MDIM + 255) / 256, 256>>>();

    const size_t nx = (size_t)BATCH * MDIM * DDIM;   // 16.7M elems each of x,y
    split_kernel<<<(unsigned)(nx / 1024), 256>>>(x, xh, xl);
    split_kernel<<<(unsigned)(nx / 1024), 256>>>(y, yh, yl);

    // GEMM1: St[n][m] = sum_d y[n,d]*x[m,d]; fused col-max over n
    {
        dim3 grid(MDIM / 128, NDIM / 128, BATCH);
        gemm_bf16x3<true><<<grid, 256, GEMM_SMEM>>>(
            yh, yl, xh, xl, St, cmax,
            DDIM, (size_t)NDIM * DDIM, (size_t)MDIM * DDIM,
            (size_t)NDIM * MDIM, MDIM);
    }
    {
        dim3 grid(MDIM / 256, NDIM / 128, BATCH);
        exp_kernel<<<grid, 256>>>();
    }
    xst_kernel<<<dim3(DDIM / 32, MDIM / 32, BATCH), 256>>>(x);

    // GEMM2: out[n][d] = sum_m Et[n,m]*xst[d,m]
    {
        dim3 grid(DDIM / 128, NDIM / 128, BATCH);
        gemm_bf16x3<false><<<grid, 256, GEMM_SMEM>>>(
            Eth, Etl, xsth, xstl, out, nullptr,
            MDIM, (size_t)NDIM * MDIM, (size_t)DDIM * MDIM,
            (size_t)NDIM * DDIM, DDIM);
    }
}